// round 13
// baseline (speedup 1.0000x reference)
#include <cuda_runtime.h>
#include <math.h>

#define NB 8
#define NN 300
#define NR 36
#define NC 256
#define NWRD 10   // ceil(300/32)
#define SPAN_P 132  // padded span (max real span <= 114)

// Scratch: per (batch, roi-slot): x1,y1,x2,y2, level(int bits), valid(int bits)
__device__ float g_roi[NB * NR * 6];

// ---------------------------------------------------------------------------
// Kernel A: per-batch NMS + selection + level assignment (unchanged from R10)
// ---------------------------------------------------------------------------
__global__ __launch_bounds__(256) void nms_kernel(const float* __restrict__ boxes,
                                                  const float* __restrict__ scores)
{
    __shared__ float    s_s[NN];
    __shared__ float    s_bx[NN * 4];
    __shared__ float    s_area[NN];
    __shared__ int      s_order[NN];
    __shared__ unsigned s_mask[NN][NWRD];
    __shared__ unsigned s_vbits[NWRD];
    __shared__ unsigned s_keepbits[NWRD];
    __shared__ int      s_sel[NR];
    __shared__ int      s_selv[NR];

    const int b = blockIdx.x;
    const int t = threadIdx.x;
    const float* bx = boxes + (size_t)b * NN * 4;
    const float* sc = scores + (size_t)b * NN;

    if (t < NWRD) s_vbits[t] = 0u;

    for (int i = t; i < NN; i += 256) {
        float v = sc[i];
        s_s[i] = (v > 0.3f) ? v : -INFINITY;
    }
    __syncthreads();

    // stable descending rank (matches jnp.argsort(-s), stable)
    for (int i = t; i < NN; i += 256) {
        float si = s_s[i];
        int r = 0;
        for (int j = 0; j < NN; j++) {
            float sj = s_s[j];
            r += (int)((sj > si) || (sj == si && j < i));
        }
        s_order[r] = i;
    }
    __syncthreads();

    for (int k = t; k < NN; k += 256) {
        int i = s_order[k];
        float x1 = bx[i*4+0], y1 = bx[i*4+1], x2 = bx[i*4+2], y2 = bx[i*4+3];
        s_bx[k*4+0] = x1; s_bx[k*4+1] = y1; s_bx[k*4+2] = x2; s_bx[k*4+3] = y2;
        s_area[k] = (x2 - x1) * (y2 - y1);
        if (s_s[i] > -INFINITY) atomicOr(&s_vbits[k >> 5], 1u << (k & 31));
    }
    __syncthreads();

    for (int task = t; task < NN * NWRD; task += 256) {
        int i = task / NWRD;
        int w = task - i * NWRD;
        float ax1 = s_bx[i*4+0], ay1 = s_bx[i*4+1];
        float ax2 = s_bx[i*4+2], ay2 = s_bx[i*4+3];
        float aarea = s_area[i];
        unsigned m = 0;
        int jend = min(NN, (w + 1) * 32);
        for (int j = max(w * 32, i + 1); j < jend; j++) {
            float ltx = fmaxf(ax1, s_bx[j*4+0]);
            float lty = fmaxf(ay1, s_bx[j*4+1]);
            float rbx = fminf(ax2, s_bx[j*4+2]);
            float rby = fminf(ay2, s_bx[j*4+3]);
            float iw = fmaxf(rbx - ltx, 0.f);
            float ih = fmaxf(rby - lty, 0.f);
            float inter = iw * ih;
            float iou = inter / (aarea + s_area[j] - inter + 1e-9f);
            if (iou > 0.7f) m |= 1u << (j & 31);
        }
        s_mask[i][w] = m;
    }
    __syncthreads();

    // greedy suppression scan on warp 0, bitmask register-resident
    if (t < 32) {
        unsigned vreg = (t < NWRD) ? s_vbits[t] : 0u;
        unsigned removed = 0u;
        for (int i = 0; i < NN; i++) {
            unsigned mrow = (t < NWRD) ? s_mask[i][t] : 0u;
            int w = i >> 5;
            unsigned bit = 1u << (i & 31);
            unsigned vw = __shfl_sync(0xffffffffu, vreg, w);
            unsigned rw = __shfl_sync(0xffffffffu, removed, w);
            if ((vw & bit) && !(rw & bit))
                removed |= mrow;
        }
        if (t < NWRD) s_keepbits[t] = vreg & ~removed;
    }
    __syncthreads();

    if (t == 0) {
        unsigned kb[NWRD];
        #pragma unroll
        for (int w = 0; w < NWRD; w++) kb[w] = s_keepbits[w];
        int cnt = 0;
        for (int i = 0; i < NN && cnt < NR; i++)
            if ((kb[i >> 5] >> (i & 31)) & 1u) { s_sel[cnt] = i; s_selv[cnt] = 1; cnt++; }
        for (int i = 0; i < NN && cnt < NR; i++)
            if (!((kb[i >> 5] >> (i & 31)) & 1u)) { s_sel[cnt] = i; s_selv[cnt] = 0; cnt++; }
    }
    __syncthreads();

    if (t < NR) {
        int k = s_sel[t];
        float x1 = s_bx[k*4+0], y1 = s_bx[k*4+1], x2 = s_bx[k*4+2], y2 = s_bx[k*4+3];
        float dx = x2 - x1, dy = y2 - y1;
        float size = sqrtf(fmaxf(dx*dx + dy*dy, 1e-12f));
        float lf = floorf(4.0f + log2f(size / 224.0f * 4.0f));
        lf = fminf(fmaxf(lf, 2.0f), 5.0f);
        int level = (int)lf - 2;
        float* o = g_roi + (size_t)(b * NR + t) * 6;
        o[0] = x1; o[1] = y1; o[2] = x2; o[3] = y2;
        o[4] = __int_as_float(level);
        o[5] = __int_as_float(s_selv[t]);
    }
}

// ---------------------------------------------------------------------------
// Kernel B: coalesced-staging bilinear ROI pooling.
// Block = (roi, batch, channel-group of 32). Per channel: cooperatively load
// the 28 needed rows' x-span CONTIGUOUSLY into shared (1 wavefront / 128B
// line instead of 32 wavefronts per scattered LDG), then 196 threads compute
// one bilinear sample each from shared and warp-reduce.
// ---------------------------------------------------------------------------
__global__ void __launch_bounds__(256, 8)
pool_kernel(const float* __restrict__ f0,
            const float* __restrict__ f1,
            const float* __restrict__ f2,
            const float* __restrict__ f3,
            float* __restrict__ out)
{
    const int r   = blockIdx.x;
    const int b   = blockIdx.y;
    const int cg  = blockIdx.z;      // channel group 0..7 (32 channels each)
    const int tid = threadIdx.x;

    __shared__ float s_info[6];
    __shared__ int   sx0[14], sx1[14];
    __shared__ float slx[14], slyv[14];
    __shared__ int   sobx[14], soby[14];
    __shared__ int   rowIdx[28], rowSlot[28];
    __shared__ int   s_rmin, s_span;
    __shared__ float s_out[32];
    __shared__ float s_tex[28][SPAN_P];

    if (tid < 6)  s_info[tid] = g_roi[(size_t)(b * NR + r) * 6 + tid];
    if (tid < 32) s_out[tid] = 0.f;
    __syncthreads();

    float* obase = out + ((size_t)(b * NR + r)) * NC + cg * 32;

    const int valid = __float_as_int(s_info[5]);
    if (!valid) {                        // block-uniform
        if (tid < 32) obase[tid] = 0.f;
        return;
    }

    const int level = __float_as_int(s_info[4]) & 3;
    const int H = 200 >> level;          // 200,100,50,25
    const int W = H;
    const float* fl = (level == 0) ? f0 : (level == 1) ? f1 : (level == 2) ? f2 : f3;

    // --- geometry (once per block) ---
    if (tid < 28) {
        int isx = (tid >= 14);
        int k = tid - (isx ? 14 : 0);
        float lo  = isx ? s_info[0] : s_info[1];
        float hi  = isx ? s_info[2] : s_info[3];
        float ext = fmaxf(hi - lo, 1.0f);
        float g = ((float)k + 0.5f) / 14.0f;
        float P = lo + ext * g;                   // unclipped -> oob test
        int lim = isx ? W : H;
        int ob = (P < -1.0f) || (P > (float)lim);
        float p = fminf(fmaxf(P, 0.0f), (float)(lim - 1));
        int p0 = (int)floorf(p);
        p0 = min(max(p0, 0), lim - 1);
        int p1 = min(p0 + 1, lim - 1);
        float lp = p - (float)p0;
        if (isx) { sx0[k] = p0; sx1[k] = p1; slx[k] = lp; sobx[k] = ob; }
        else     { rowIdx[2*k] = p0; rowIdx[2*k+1] = p1; slyv[k] = lp; soby[k] = ob; }
    }
    __syncthreads();

    if (tid == 0) {
        int rmin = 1 << 30, rmax = -1;
        for (int i = 0; i < 14; i++)
            if (!sobx[i]) { rmin = min(rmin, sx0[i]); rmax = max(rmax, sx1[i]); }
        int span = (rmax < 0) ? 0 : (rmax - rmin + 1);
        if (span > 128) span = 128;               // defensive (real max <= 114)
        s_rmin = (rmax < 0) ? 0 : rmin;
        s_span = span;
        // row dedup among VALID rows only (never alias a valid row to an
        // unloaded oob row)
        for (int t2 = 0; t2 < 28; t2++) {
            int s = t2;
            if (!soby[t2 >> 1]) {
                for (int u = 0; u < t2; u++)
                    if (!soby[u >> 1] && rowIdx[u] == rowIdx[t2]) { s = u; break; }
            }
            rowSlot[t2] = s;
        }
    }
    __syncthreads();

    const int rmin = s_rmin;
    const int span = s_span;

    // --- per-channel: coalesced stage + compute ---
    for (int ch = 0; ch < 32; ch++) {
        const int c = cg * 32 + ch;
        const float* plane = fl + (size_t)(b * NC + c) * (size_t)(H * W);

        // stage 28 rows x span, contiguous per row (coalesced)
        for (int i = tid; i < 28 * 128; i += 256) {
            int row = i >> 7;
            int col = i & 127;
            if (col < span && rowSlot[row] == row && !soby[row >> 1])
                s_tex[row][col] = __ldg(plane + rowIdx[row] * W + rmin + col);
        }
        __syncthreads();

        float v = 0.f;
        if (tid < 196) {
            int iy = tid / 14;
            int ix = tid - iy * 14;
            if (!soby[iy] && !sobx[ix]) {
                int ra = rowSlot[2 * iy];
                int rb = rowSlot[2 * iy + 1];
                int cx0 = min(max(sx0[ix] - rmin, 0), SPAN_P - 1);
                int cx1 = min(max(sx1[ix] - rmin, 0), SPAN_P - 1);
                float ly = slyv[iy], lx = slx[ix];
                float f00 = s_tex[ra][cx0];
                float f01 = s_tex[ra][cx1];
                float f10 = s_tex[rb][cx0];
                float f11 = s_tex[rb][cx1];
                float top = f00 * (1.f - ly) + f10 * ly;
                float bot = f01 * (1.f - ly) + f11 * ly;
                v = top * (1.f - lx) + bot * lx;
            }
        }
        // warp reduce, then one atomic per warp into the channel accumulator
        #pragma unroll
        for (int o = 16; o > 0; o >>= 1)
            v += __shfl_down_sync(0xffffffffu, v, o);
        if ((tid & 31) == 0 && v != 0.f)
            atomicAdd(&s_out[ch], v);
        __syncthreads();   // s_out[ch] complete; s_tex safe to overwrite
    }

    if (tid < 32) obase[tid] = s_out[tid] * (1.f / 196.f);
}

// ---------------------------------------------------------------------------
extern "C" void kernel_launch(void* const* d_in, const int* in_sizes, int n_in,
                              void* d_out, int out_size)
{
    // Identify inputs by element count (all six are distinct sizes).
    const float* boxes  = nullptr;
    const float* scores = nullptr;
    const float* f0 = nullptr;
    const float* f1 = nullptr;
    const float* f2 = nullptr;
    const float* f3 = nullptr;
    for (int i = 0; i < n_in; i++) {
        switch (in_sizes[i]) {
            case 9600:     boxes  = (const float*)d_in[i]; break;
            case 2400:     scores = (const float*)d_in[i]; break;
            case 81920000: f0     = (const float*)d_in[i]; break;
            case 20480000: f1     = (const float*)d_in[i]; break;
            case 5120000:  f2     = (const float*)d_in[i]; break;
            case 1280000:  f3     = (const float*)d_in[i]; break;
            default: break;
        }
    }
    if (!boxes || !scores || !f0 || !f1 || !f2 || !f3) {
        boxes  = (const float*)d_in[0];
        scores = (const float*)d_in[1];
        f0     = (const float*)d_in[2];
        f1     = (const float*)d_in[3];
        f2     = (const float*)d_in[4];
        f3     = (const float*)d_in[5];
    }
    float* out = (float*)d_out;

    nms_kernel<<<NB, 256>>>(boxes, scores);
    dim3 g(NR, NB, 8);
    pool_kernel<<<g, 256>>>(f0, f1, f2, f3, out);
}

// round 16
// speedup vs baseline: 3.0511x; 3.0511x over previous
#include <cuda_runtime.h>
#include <math.h>

#define NB 8
#define NN 300
#define NR 36
#define NC 256
#define NWRD 10   // ceil(300/32)

// Scratch: per (batch, roi-slot): x1,y1,x2,y2, level(int bits), valid(int bits)
__device__ float g_roi[NB * NR * 6];

// ---------------------------------------------------------------------------
// Kernel A: per-batch NMS + selection + level assignment (verified, unchanged)
// ---------------------------------------------------------------------------
__global__ __launch_bounds__(256) void nms_kernel(const float* __restrict__ boxes,
                                                  const float* __restrict__ scores)
{
    __shared__ float    s_s[NN];
    __shared__ float    s_bx[NN * 4];
    __shared__ float    s_area[NN];
    __shared__ int      s_order[NN];
    __shared__ unsigned s_mask[NN][NWRD];
    __shared__ unsigned s_vbits[NWRD];
    __shared__ unsigned s_keepbits[NWRD];
    __shared__ int      s_sel[NR];
    __shared__ int      s_selv[NR];

    const int b = blockIdx.x;
    const int t = threadIdx.x;
    const float* bx = boxes + (size_t)b * NN * 4;
    const float* sc = scores + (size_t)b * NN;

    if (t < NWRD) s_vbits[t] = 0u;

    for (int i = t; i < NN; i += 256) {
        float v = sc[i];
        s_s[i] = (v > 0.3f) ? v : -INFINITY;
    }
    __syncthreads();

    // stable descending rank (matches jnp.argsort(-s), stable)
    for (int i = t; i < NN; i += 256) {
        float si = s_s[i];
        int r = 0;
        for (int j = 0; j < NN; j++) {
            float sj = s_s[j];
            r += (int)((sj > si) || (sj == si && j < i));
        }
        s_order[r] = i;
    }
    __syncthreads();

    for (int k = t; k < NN; k += 256) {
        int i = s_order[k];
        float x1 = bx[i*4+0], y1 = bx[i*4+1], x2 = bx[i*4+2], y2 = bx[i*4+3];
        s_bx[k*4+0] = x1; s_bx[k*4+1] = y1; s_bx[k*4+2] = x2; s_bx[k*4+3] = y2;
        s_area[k] = (x2 - x1) * (y2 - y1);
        if (s_s[i] > -INFINITY) atomicOr(&s_vbits[k >> 5], 1u << (k & 31));
    }
    __syncthreads();

    for (int task = t; task < NN * NWRD; task += 256) {
        int i = task / NWRD;
        int w = task - i * NWRD;
        float ax1 = s_bx[i*4+0], ay1 = s_bx[i*4+1];
        float ax2 = s_bx[i*4+2], ay2 = s_bx[i*4+3];
        float aarea = s_area[i];
        unsigned m = 0;
        int jend = min(NN, (w + 1) * 32);
        for (int j = max(w * 32, i + 1); j < jend; j++) {
            float ltx = fmaxf(ax1, s_bx[j*4+0]);
            float lty = fmaxf(ay1, s_bx[j*4+1]);
            float rbx = fminf(ax2, s_bx[j*4+2]);
            float rby = fminf(ay2, s_bx[j*4+3]);
            float iw = fmaxf(rbx - ltx, 0.f);
            float ih = fmaxf(rby - lty, 0.f);
            float inter = iw * ih;
            float iou = inter / (aarea + s_area[j] - inter + 1e-9f);
            if (iou > 0.7f) m |= 1u << (j & 31);
        }
        s_mask[i][w] = m;
    }
    __syncthreads();

    // greedy suppression scan on warp 0, bitmask register-resident
    if (t < 32) {
        unsigned vreg = (t < NWRD) ? s_vbits[t] : 0u;
        unsigned removed = 0u;
        for (int i = 0; i < NN; i++) {
            unsigned mrow = (t < NWRD) ? s_mask[i][t] : 0u;
            int w = i >> 5;
            unsigned bit = 1u << (i & 31);
            unsigned vw = __shfl_sync(0xffffffffu, vreg, w);
            unsigned rw = __shfl_sync(0xffffffffu, removed, w);
            if ((vw & bit) && !(rw & bit))
                removed |= mrow;
        }
        if (t < NWRD) s_keepbits[t] = vreg & ~removed;
    }
    __syncthreads();

    if (t == 0) {
        unsigned kb[NWRD];
        #pragma unroll
        for (int w = 0; w < NWRD; w++) kb[w] = s_keepbits[w];
        int cnt = 0;
        for (int i = 0; i < NN && cnt < NR; i++)
            if ((kb[i >> 5] >> (i & 31)) & 1u) { s_sel[cnt] = i; s_selv[cnt] = 1; cnt++; }
        for (int i = 0; i < NN && cnt < NR; i++)
            if (!((kb[i >> 5] >> (i & 31)) & 1u)) { s_sel[cnt] = i; s_selv[cnt] = 0; cnt++; }
    }
    __syncthreads();

    if (t < NR) {
        int k = s_sel[t];
        float x1 = s_bx[k*4+0], y1 = s_bx[k*4+1], x2 = s_bx[k*4+2], y2 = s_bx[k*4+3];
        float dx = x2 - x1, dy = y2 - y1;
        float size = sqrtf(fmaxf(dx*dx + dy*dy, 1e-12f));
        float lf = floorf(4.0f + log2f(size / 224.0f * 4.0f));
        lf = fminf(fmaxf(lf, 2.0f), 5.0f);
        int level = (int)lf - 2;
        float* o = g_roi + (size_t)(b * NR + t) * 6;
        o[0] = x1; o[1] = y1; o[2] = x2; o[3] = y2;
        o[4] = __int_as_float(level);
        o[5] = __int_as_float(s_selv[t]);
    }
}

// ---------------------------------------------------------------------------
// Kernel B: x-coalesced bilinear ROI pooling (no staging, no inner barriers).
// Block = (roi, batch, channel-group of 16). blockDim = 256 = (tx:16, ty:16).
//   tx = sample x-index (0..13 active), ty = channel within group.
// Lanes 0-13 / 16-29 of a warp read addresses within one ROI row span
// (<= ~456B -> 2-5 cache lines) for two channels -> ~4-10 L1tex wavefronts
// per LDG instead of 32 with the channel-per-lane mapping.
// Channel sum = shfl_xor butterfly over the 16-lane x-group.
// ---------------------------------------------------------------------------
__global__ void __launch_bounds__(256)
pool_kernel(const float* __restrict__ f0,
            const float* __restrict__ f1,
            const float* __restrict__ f2,
            const float* __restrict__ f3,
            float* __restrict__ out)
{
    const int r   = blockIdx.x;
    const int b   = blockIdx.y;
    const int cg  = blockIdx.z;           // 16 groups of 16 channels
    const int tid = threadIdx.x;
    const int tx  = tid & 15;             // sample-x lane
    const int ty  = tid >> 4;             // channel within group
    const int c   = cg * 16 + ty;

    __shared__ float s_info[6];
    __shared__ int   sx0[16], sx1[16];
    __shared__ float slx[16];
    __shared__ int   sobx[16];
    __shared__ int   sy0[14], sy1[14];
    __shared__ float sly[14];
    __shared__ int   soby[14];

    if (tid < 6) s_info[tid] = g_roi[(size_t)(b * NR + r) * 6 + tid];
    __syncthreads();

    float* o = out + ((size_t)(b * NR + r)) * NC + c;

    const int valid = __float_as_int(s_info[5]);
    if (!valid) {                          // block-uniform
        if (tx == 0) *o = 0.f;
        return;
    }

    const int level = __float_as_int(s_info[4]) & 3;
    const int H = 200 >> level;            // 200,100,50,25
    const int W = H;
    const float* fl = (level == 0) ? f0 : (level == 1) ? f1 : (level == 2) ? f2 : f3;

    // geometry (28 threads); pad x-slots 14,15 as oob
    if (tid < 30) {
        int isx = (tid >= 14);
        int k = tid - (isx ? 14 : 0);
        float lo  = isx ? s_info[0] : s_info[1];
        float hi  = isx ? s_info[2] : s_info[3];
        float ext = fmaxf(hi - lo, 1.0f);
        float g = ((float)k + 0.5f) / 14.0f;
        float P = lo + ext * g;            // unclipped -> oob test
        int lim = isx ? W : H;
        int ob = (P < -1.0f) || (P > (float)lim) || (k >= 14);
        float p = fminf(fmaxf(P, 0.0f), (float)(lim - 1));
        int p0 = (int)floorf(p);
        p0 = min(max(p0, 0), lim - 1);
        int p1 = min(p0 + 1, lim - 1);
        float lp = p - (float)p0;
        if (isx) { sx0[k] = ob ? 0 : p0; sx1[k] = ob ? 0 : p1; slx[k] = lp; sobx[k] = ob; }
        else if (k < 14) { sy0[k] = p0; sy1[k] = p1; sly[k] = lp; soby[k] = ob; }
    }
    __syncthreads();

    // per-lane x geometry in registers
    const int   x0  = sx0[tx];
    const int   x1  = sx1[tx];
    const float lx  = slx[tx];
    const int   obx = sobx[tx];
    const float wx0 = 1.f - lx;

    const float* plane = fl + (size_t)(b * NC + c) * (size_t)(H * W);

    float sum = 0.f;
    #pragma unroll
    for (int iy = 0; iy < 14; iy++) {
        if (soby[iy]) continue;            // block-uniform branch
        const float* ra = plane + sy0[iy] * W;
        const float* rb = plane + sy1[iy] * W;
        float ly = sly[iy];
        float wy = 1.f - ly;
        if (!obx) {
            float f00 = __ldg(ra + x0);
            float f01 = __ldg(ra + x1);
            float f10 = __ldg(rb + x0);
            float f11 = __ldg(rb + x1);
            float top = f00 * wy + f10 * ly;
            float bot = f01 * wy + f11 * ly;
            sum += top * wx0 + bot * lx;
        }
    }

    // reduce over the 16-lane x-group (xor offsets < 16 stay in-group)
    #pragma unroll
    for (int ofs = 8; ofs > 0; ofs >>= 1)
        sum += __shfl_xor_sync(0xffffffffu, sum, ofs);

    if (tx == 0) *o = sum * (1.f / 196.f);
}

// ---------------------------------------------------------------------------
extern "C" void kernel_launch(void* const* d_in, const int* in_sizes, int n_in,
                              void* d_out, int out_size)
{
    // Identify inputs by element count (all six are distinct sizes).
    const float* boxes  = nullptr;
    const float* scores = nullptr;
    const float* f0 = nullptr;
    const float* f1 = nullptr;
    const float* f2 = nullptr;
    const float* f3 = nullptr;
    for (int i = 0; i < n_in; i++) {
        switch (in_sizes[i]) {
            case 9600:     boxes  = (const float*)d_in[i]; break;
            case 2400:     scores = (const float*)d_in[i]; break;
            case 81920000: f0     = (const float*)d_in[i]; break;
            case 20480000: f1     = (const float*)d_in[i]; break;
            case 5120000:  f2     = (const float*)d_in[i]; break;
            case 1280000:  f3     = (const float*)d_in[i]; break;
            default: break;
        }
    }
    if (!boxes || !scores || !f0 || !f1 || !f2 || !f3) {
        boxes  = (const float*)d_in[0];
        scores = (const float*)d_in[1];
        f0     = (const float*)d_in[2];
        f1     = (const float*)d_in[3];
        f2     = (const float*)d_in[4];
        f3     = (const float*)d_in[5];
    }
    float* out = (float*)d_out;

    nms_kernel<<<NB, 256>>>(boxes, scores);
    dim3 g(NR, NB, 16);
    pool_kernel<<<g, 256>>>(f0, f1, f2, f3, out);
}

// round 17
// speedup vs baseline: 3.0617x; 1.0035x over previous
#include <cuda_runtime.h>
#include <math.h>

#define NB 8
#define NN 300
#define NR 36
#define NC 256
#define NWRD 10   // ceil(300/32)

// Scratch: per (batch, roi-slot): x1,y1,x2,y2, level(int bits), valid(int bits)
__device__ float g_roi[NB * NR * 6];

// ---------------------------------------------------------------------------
// Kernel A: per-batch NMS + selection + level assignment (verified, unchanged)
// ---------------------------------------------------------------------------
__global__ __launch_bounds__(256) void nms_kernel(const float* __restrict__ boxes,
                                                  const float* __restrict__ scores)
{
    __shared__ float    s_s[NN];
    __shared__ float    s_bx[NN * 4];
    __shared__ float    s_area[NN];
    __shared__ int      s_order[NN];
    __shared__ unsigned s_mask[NN][NWRD];
    __shared__ unsigned s_vbits[NWRD];
    __shared__ unsigned s_keepbits[NWRD];
    __shared__ int      s_sel[NR];
    __shared__ int      s_selv[NR];

    const int b = blockIdx.x;
    const int t = threadIdx.x;
    const float* bx = boxes + (size_t)b * NN * 4;
    const float* sc = scores + (size_t)b * NN;

    if (t < NWRD) s_vbits[t] = 0u;

    for (int i = t; i < NN; i += 256) {
        float v = sc[i];
        s_s[i] = (v > 0.3f) ? v : -INFINITY;
    }
    __syncthreads();

    // stable descending rank (matches jnp.argsort(-s), stable)
    for (int i = t; i < NN; i += 256) {
        float si = s_s[i];
        int r = 0;
        for (int j = 0; j < NN; j++) {
            float sj = s_s[j];
            r += (int)((sj > si) || (sj == si && j < i));
        }
        s_order[r] = i;
    }
    __syncthreads();

    for (int k = t; k < NN; k += 256) {
        int i = s_order[k];
        float x1 = bx[i*4+0], y1 = bx[i*4+1], x2 = bx[i*4+2], y2 = bx[i*4+3];
        s_bx[k*4+0] = x1; s_bx[k*4+1] = y1; s_bx[k*4+2] = x2; s_bx[k*4+3] = y2;
        s_area[k] = (x2 - x1) * (y2 - y1);
        if (s_s[i] > -INFINITY) atomicOr(&s_vbits[k >> 5], 1u << (k & 31));
    }
    __syncthreads();

    for (int task = t; task < NN * NWRD; task += 256) {
        int i = task / NWRD;
        int w = task - i * NWRD;
        float ax1 = s_bx[i*4+0], ay1 = s_bx[i*4+1];
        float ax2 = s_bx[i*4+2], ay2 = s_bx[i*4+3];
        float aarea = s_area[i];
        unsigned m = 0;
        int jend = min(NN, (w + 1) * 32);
        for (int j = max(w * 32, i + 1); j < jend; j++) {
            float ltx = fmaxf(ax1, s_bx[j*4+0]);
            float lty = fmaxf(ay1, s_bx[j*4+1]);
            float rbx = fminf(ax2, s_bx[j*4+2]);
            float rby = fminf(ay2, s_bx[j*4+3]);
            float iw = fmaxf(rbx - ltx, 0.f);
            float ih = fmaxf(rby - lty, 0.f);
            float inter = iw * ih;
            float iou = inter / (aarea + s_area[j] - inter + 1e-9f);
            if (iou > 0.7f) m |= 1u << (j & 31);
        }
        s_mask[i][w] = m;
    }
    __syncthreads();

    // greedy suppression scan on warp 0, bitmask register-resident
    if (t < 32) {
        unsigned vreg = (t < NWRD) ? s_vbits[t] : 0u;
        unsigned removed = 0u;
        for (int i = 0; i < NN; i++) {
            unsigned mrow = (t < NWRD) ? s_mask[i][t] : 0u;
            int w = i >> 5;
            unsigned bit = 1u << (i & 31);
            unsigned vw = __shfl_sync(0xffffffffu, vreg, w);
            unsigned rw = __shfl_sync(0xffffffffu, removed, w);
            if ((vw & bit) && !(rw & bit))
                removed |= mrow;
        }
        if (t < NWRD) s_keepbits[t] = vreg & ~removed;
    }
    __syncthreads();

    if (t == 0) {
        unsigned kb[NWRD];
        #pragma unroll
        for (int w = 0; w < NWRD; w++) kb[w] = s_keepbits[w];
        int cnt = 0;
        for (int i = 0; i < NN && cnt < NR; i++)
            if ((kb[i >> 5] >> (i & 31)) & 1u) { s_sel[cnt] = i; s_selv[cnt] = 1; cnt++; }
        for (int i = 0; i < NN && cnt < NR; i++)
            if (!((kb[i >> 5] >> (i & 31)) & 1u)) { s_sel[cnt] = i; s_selv[cnt] = 0; cnt++; }
    }
    __syncthreads();

    if (t < NR) {
        int k = s_sel[t];
        float x1 = s_bx[k*4+0], y1 = s_bx[k*4+1], x2 = s_bx[k*4+2], y2 = s_bx[k*4+3];
        float dx = x2 - x1, dy = y2 - y1;
        float size = sqrtf(fmaxf(dx*dx + dy*dy, 1e-12f));
        float lf = floorf(4.0f + log2f(size / 224.0f * 4.0f));
        lf = fminf(fmaxf(lf, 2.0f), 5.0f);
        int level = (int)lf - 2;
        float* o = g_roi + (size_t)(b * NR + t) * 6;
        o[0] = x1; o[1] = y1; o[2] = x2; o[3] = y2;
        o[4] = __int_as_float(level);
        o[5] = __int_as_float(s_selv[t]);
    }
}

// ---------------------------------------------------------------------------
// Kernel B: x-coalesced bilinear ROI pooling (no staging, no inner barriers).
// Block = (roi, batch, channel-group of 16). blockDim = 256 = (tx:16, ty:16).
//   tx = sample x-index (0..13 active), ty = channel within group.
// Lanes 0-13 / 16-29 of a warp read addresses within one ROI row span
// (<= ~456B -> 2-5 cache lines) for two channels -> ~4-10 L1tex wavefronts
// per LDG instead of 32 with the channel-per-lane mapping.
// Channel sum = shfl_xor butterfly over the 16-lane x-group.
// ---------------------------------------------------------------------------
__global__ void __launch_bounds__(256)
pool_kernel(const float* __restrict__ f0,
            const float* __restrict__ f1,
            const float* __restrict__ f2,
            const float* __restrict__ f3,
            float* __restrict__ out)
{
    const int r   = blockIdx.x;
    const int b   = blockIdx.y;
    const int cg  = blockIdx.z;           // 16 groups of 16 channels
    const int tid = threadIdx.x;
    const int tx  = tid & 15;             // sample-x lane
    const int ty  = tid >> 4;             // channel within group
    const int c   = cg * 16 + ty;

    __shared__ float s_info[6];
    __shared__ int   sx0[16], sx1[16];
    __shared__ float slx[16];
    __shared__ int   sobx[16];
    __shared__ int   sy0[14], sy1[14];
    __shared__ float sly[14];
    __shared__ int   soby[14];

    if (tid < 6) s_info[tid] = g_roi[(size_t)(b * NR + r) * 6 + tid];
    __syncthreads();

    float* o = out + ((size_t)(b * NR + r)) * NC + c;

    const int valid = __float_as_int(s_info[5]);
    if (!valid) {                          // block-uniform
        if (tx == 0) *o = 0.f;
        return;
    }

    const int level = __float_as_int(s_info[4]) & 3;
    const int H = 200 >> level;            // 200,100,50,25
    const int W = H;
    const float* fl = (level == 0) ? f0 : (level == 1) ? f1 : (level == 2) ? f2 : f3;

    // geometry (28 threads); pad x-slots 14,15 as oob
    if (tid < 30) {
        int isx = (tid >= 14);
        int k = tid - (isx ? 14 : 0);
        float lo  = isx ? s_info[0] : s_info[1];
        float hi  = isx ? s_info[2] : s_info[3];
        float ext = fmaxf(hi - lo, 1.0f);
        float g = ((float)k + 0.5f) / 14.0f;
        float P = lo + ext * g;            // unclipped -> oob test
        int lim = isx ? W : H;
        int ob = (P < -1.0f) || (P > (float)lim) || (k >= 14);
        float p = fminf(fmaxf(P, 0.0f), (float)(lim - 1));
        int p0 = (int)floorf(p);
        p0 = min(max(p0, 0), lim - 1);
        int p1 = min(p0 + 1, lim - 1);
        float lp = p - (float)p0;
        if (isx) { sx0[k] = ob ? 0 : p0; sx1[k] = ob ? 0 : p1; slx[k] = lp; sobx[k] = ob; }
        else if (k < 14) { sy0[k] = p0; sy1[k] = p1; sly[k] = lp; soby[k] = ob; }
    }
    __syncthreads();

    // per-lane x geometry in registers
    const int   x0  = sx0[tx];
    const int   x1  = sx1[tx];
    const float lx  = slx[tx];
    const int   obx = sobx[tx];
    const float wx0 = 1.f - lx;

    const float* plane = fl + (size_t)(b * NC + c) * (size_t)(H * W);

    float sum = 0.f;
    #pragma unroll
    for (int iy = 0; iy < 14; iy++) {
        if (soby[iy]) continue;            // block-uniform branch
        const float* ra = plane + sy0[iy] * W;
        const float* rb = plane + sy1[iy] * W;
        float ly = sly[iy];
        float wy = 1.f - ly;
        if (!obx) {
            float f00 = __ldg(ra + x0);
            float f01 = __ldg(ra + x1);
            float f10 = __ldg(rb + x0);
            float f11 = __ldg(rb + x1);
            float top = f00 * wy + f10 * ly;
            float bot = f01 * wy + f11 * ly;
            sum += top * wx0 + bot * lx;
        }
    }

    // reduce over the 16-lane x-group (xor offsets < 16 stay in-group)
    #pragma unroll
    for (int ofs = 8; ofs > 0; ofs >>= 1)
        sum += __shfl_xor_sync(0xffffffffu, sum, ofs);

    if (tx == 0) *o = sum * (1.f / 196.f);
}

// ---------------------------------------------------------------------------
extern "C" void kernel_launch(void* const* d_in, const int* in_sizes, int n_in,
                              void* d_out, int out_size)
{
    // Identify inputs by element count (all six are distinct sizes).
    const float* boxes  = nullptr;
    const float* scores = nullptr;
    const float* f0 = nullptr;
    const float* f1 = nullptr;
    const float* f2 = nullptr;
    const float* f3 = nullptr;
    for (int i = 0; i < n_in; i++) {
        switch (in_sizes[i]) {
            case 9600:     boxes  = (const float*)d_in[i]; break;
            case 2400:     scores = (const float*)d_in[i]; break;
            case 81920000: f0     = (const float*)d_in[i]; break;
            case 20480000: f1     = (const float*)d_in[i]; break;
            case 5120000:  f2     = (const float*)d_in[i]; break;
            case 1280000:  f3     = (const float*)d_in[i]; break;
            default: break;
        }
    }
    if (!boxes || !scores || !f0 || !f1 || !f2 || !f3) {
        boxes  = (const float*)d_in[0];
        scores = (const float*)d_in[1];
        f0     = (const float*)d_in[2];
        f1     = (const float*)d_in[3];
        f2     = (const float*)d_in[4];
        f3     = (const float*)d_in[5];
    }
    float* out = (float*)d_out;

    nms_kernel<<<NB, 256>>>(boxes, scores);
    dim3 g(NR, NB, 16);
    pool_kernel<<<g, 256>>>(f0, f1, f2, f3, out);
}